// round 8
// baseline (speedup 1.0000x reference)
#include <cuda_runtime.h>
#include <math.h>

// Problem constants
constexpr int T_ = 256;
constexpr int B_ = 1024;
constexpr int Y_ = 32;
constexpr int H_ = 1024;
constexpr int R_ = 512;
constexpr int R3_ = 3 * R_;          // 1536
constexpr int CHUNK_ = 32;           // timesteps per decoder chunk
constexpr int NCHUNK_ = T_ / CHUNK_; // 8
constexpr int ROWS_ = CHUNK_ * B_;   // 32768 rows per decoder chunk
constexpr int NBLK_ = 296;           // persistent grid: 2 blocks per SM (148 SMs)

// -------- device scratch (static: no allocations allowed) --------
__device__ float g_h0[B_ * R_];                     // 2 MB
__device__ float g_h1[B_ * R_];                     // 2 MB
__device__ float g_gi[B_ * R3_];                    // 6 MB (gi0, then gi1)
__device__ float g_gh[B_ * R3_];                    // 6 MB (gh layer 0)
__device__ float g_gh1[B_ * R3_];                   // 6 MB (gh layer 1)
__device__ float g_h1all[(size_t)T_ * B_ * R_];     // 512 MB: h1 entering step t
__device__ float g_d1[(size_t)ROWS_ * H_];          // 128 MB
__device__ float g_d2[(size_t)ROWS_ * H_];          // 128 MB
__device__ float g_rowsum[T_ * B_];                 // 1 MB per-row NLL

// -------- software grid barrier (generation counter; monotonic gen is
// replay-safe: arrive always returns to 0, gen need not be reset) --------
__device__ unsigned g_bar_arrive;
__device__ volatile unsigned g_bar_gen;

__device__ __forceinline__ void grid_sync()
{
    __threadfence();
    __syncthreads();
    if (threadIdx.x == 0) {
        unsigned gen = g_bar_gen;
        if (atomicAdd(&g_bar_arrive, 1u) == (unsigned)gridDim.x - 1u) {
            g_bar_arrive = 0u;
            __threadfence();
            g_bar_gen = gen + 1u;
        } else {
            while (g_bar_gen == gen) { __nanosleep(32); }
        }
        __threadfence();
    }
    __syncthreads();
}

// ---------------------------------------------------------------
// One 64xBN output tile of C[M,N] = A[M,K] @ W[N,K]^T + bias[N].
// 256 threads, BK=8. BN in {64,128}. K multiple of 8.
// As: 8x64 floats, Ws: 8xBN floats (shared, caller-provided).
// ---------------------------------------------------------------
template<int BN>
__device__ __forceinline__ void gemm_tile(
    const float* __restrict__ A, const float* __restrict__ W,
    const float* __restrict__ bias, float* __restrict__ C,
    int N, int K, int bm, int bn, float* As, float* Ws)
{
    constexpr int TN = BN / 16;             // 8 or 4 cols per thread
    const int tid = threadIdx.x;
    const int ty = (tid >> 4) << 2;         // 0..60 (4 rows per thread)
    const int tx = (tid & 15) * TN;

    const int aRow = tid >> 2;              // 0..63
    const int aCol = (tid & 3) << 1;        // float2
    const float* Ap = A + (size_t)(bm + aRow) * K + aCol;

    const int wRow = (BN == 128) ? (tid >> 1) : (tid >> 2);
    const int wCol = (BN == 128) ? ((tid & 1) << 2) : ((tid & 3) << 1);
    const float* Wp = W + (size_t)(bn + wRow) * K + wCol;

    float acc[4][TN];
#pragma unroll
    for (int i = 0; i < 4; i++)
#pragma unroll
        for (int j = 0; j < TN; j++) acc[i][j] = 0.f;

    for (int k0 = 0; k0 < K; k0 += 8) {
        float2 a2 = *reinterpret_cast<const float2*>(Ap + k0);
        float4 w4;
        float2 w2;
        if constexpr (BN == 128) {
            w4 = *reinterpret_cast<const float4*>(Wp + k0);
        } else {
            w2 = *reinterpret_cast<const float2*>(Wp + k0);
        }
        __syncthreads();
        As[(aCol)     * 64 + aRow] = a2.x;
        As[(aCol + 1) * 64 + aRow] = a2.y;
        if constexpr (BN == 128) {
            Ws[(wCol)     * BN + wRow] = w4.x;
            Ws[(wCol + 1) * BN + wRow] = w4.y;
            Ws[(wCol + 2) * BN + wRow] = w4.z;
            Ws[(wCol + 3) * BN + wRow] = w4.w;
        } else {
            Ws[(wCol)     * BN + wRow] = w2.x;
            Ws[(wCol + 1) * BN + wRow] = w2.y;
        }
        __syncthreads();
#pragma unroll
        for (int k = 0; k < 8; k++) {
            float4 ra = *reinterpret_cast<const float4*>(&As[k * 64 + ty]);
            float av[4] = {ra.x, ra.y, ra.z, ra.w};
            float bv[TN];
#pragma unroll
            for (int j = 0; j < TN; j += 4) {
                float4 b = *reinterpret_cast<const float4*>(&Ws[k * BN + tx + j]);
                bv[j] = b.x; bv[j + 1] = b.y; bv[j + 2] = b.z; bv[j + 3] = b.w;
            }
#pragma unroll
            for (int i = 0; i < 4; i++)
#pragma unroll
                for (int j = 0; j < TN; j++)
                    acc[i][j] = fmaf(av[i], bv[j], acc[i][j]);
        }
    }

#pragma unroll
    for (int i = 0; i < 4; i++) {
        float* Cp = C + (size_t)(bm + ty + i) * N + bn + tx;
#pragma unroll
        for (int j = 0; j < TN; j++)
            Cp[j] = acc[i][j] + bias[bn + tx + j];
    }
}

// GRU gate fuse over the full grid (grid-stride): h = (1-z)*n + z*h
__device__ __forceinline__ void gate_phase(
    const float* __restrict__ gi, const float* __restrict__ gh,
    float* __restrict__ h, float* __restrict__ slot)
{
    const int stride = gridDim.x * blockDim.x;
    for (int idx = blockIdx.x * blockDim.x + threadIdx.x;
         idx < B_ * R_; idx += stride) {
        const int b = idx >> 9;          // /R (R=512)
        const int j = idx & (R_ - 1);
        const float* gib = gi + (size_t)b * R3_;
        const float* ghb = gh + (size_t)b * R3_;
        const float ir = gib[j],          hr = ghb[j];
        const float iz = gib[R_ + j],     hz = ghb[R_ + j];
        const float in = gib[2 * R_ + j], hn = ghb[2 * R_ + j];
        const float r = 1.f / (1.f + expf(-(ir + hr)));
        const float z = 1.f / (1.f + expf(-(iz + hz)));
        const float n = tanhf(in + r * hn);
        const float hv = (1.f - z) * n + z * h[idx];
        h[idx] = hv;
        if (slot) slot[idx] = hv;
    }
}

// ---------------------------------------------------------------
// Persistent recurrence kernel: the entire T=256 scan in ONE launch.
// grid = 296 blocks, 256 threads; __launch_bounds__(256,2) guarantees
// 2 CTAs/SM co-residency -> the software grid barrier cannot deadlock.
// ---------------------------------------------------------------
__global__ void __launch_bounds__(256, 2) rnn_persistent(
    const float* __restrict__ y,
    const float* __restrict__ wih0, const float* __restrict__ whh0,
    const float* __restrict__ bih0, const float* __restrict__ bhh0,
    const float* __restrict__ wih1, const float* __restrict__ whh1,
    const float* __restrict__ bih1, const float* __restrict__ bhh1)
{
    __shared__ float As[8 * 64];
    __shared__ float Ws[8 * 128];
    const int bid = blockIdx.x;

    for (int t = 0; t < T_; t++) {
        const float* y_t = y + (size_t)t * B_ * Y_;

        // P0: gh0 = h0@whh0^T (tiles 0..191), gh1 = h1@whh1^T (192..383),
        //     gi0 = y_t@wih0^T (K=32, folded onto the gh0 tiles).
        //     gh1 is independent of gate0 -> compute it here for balance.
        for (int tile = bid; tile < 384; tile += NBLK_) {
            const int tt = (tile < 192) ? tile : tile - 192;
            const int bm = (tt / 12) * 64;
            const int bn = (tt % 12) * 128;
            if (tile < 192) {
                gemm_tile<128>(g_h0, whh0, bhh0, g_gh, R3_, R_, bm, bn, As, Ws);
                gemm_tile<128>(y_t, wih0, bih0, g_gi, R3_, Y_, bm, bn, As, Ws);
            } else {
                gemm_tile<128>(g_h1, whh1, bhh1, g_gh1, R3_, R_, bm, bn, As, Ws);
            }
        }
        grid_sync();

        // P1: gate layer 0 -> new h0
        gate_phase(g_gi, g_gh, g_h0, nullptr);
        grid_sync();

        // P2: gi1 = h0'@wih1^T, 64x64 tiles (384 tiles) for wave balance
        for (int tile = bid; tile < 384; tile += NBLK_) {
            const int bm = (tile / 24) * 64;
            const int bn = (tile % 24) * 64;
            gemm_tile<64>(g_h0, wih1, bih1, g_gi, R3_, R_, bm, bn, As, Ws);
        }
        grid_sync();

        // P3: gate layer 1 -> new h1 (+ record state entering step t+1)
        float* slot = (t + 1 < T_) ? (g_h1all + (size_t)(t + 1) * B_ * R_)
                                   : nullptr;
        gate_phase(g_gi, g_gh1, g_h1, slot);
        grid_sync();
    }
}

// ---------------------------------------------------------------
// Decoder GEMM (big, fully parallel): C = act(A@W^T + b), BM=64 BN=128 BK=8
// ---------------------------------------------------------------
__global__ void __launch_bounds__(256, 2) sgemm_bias_act(
    const float* __restrict__ A, const float* __restrict__ W,
    const float* __restrict__ bias, float* __restrict__ C,
    int M, int N, int K, int relu)
{
    __shared__ float As[8 * 64];
    __shared__ float Ws[8 * 128];
    const int tid = threadIdx.x;
    const int bm = blockIdx.y * 64;
    const int bn = blockIdx.x * 128;

    const int ty = (tid >> 4) << 2;
    const int tx = (tid & 15) << 3;

    gemm_tile<128>(A, W, bias, C, N, K, bm, bn, As, Ws);

    if (relu) {
#pragma unroll
        for (int i = 0; i < 4; i++) {
            float* Cp = C + (size_t)(bm + ty + i) * N + bn + tx;
#pragma unroll
            for (int j = 0; j < 8; j++) Cp[j] = fmaxf(Cp[j], 0.f);
        }
    }
}

// ---------------------------------------------------------------
__global__ void init_kernel()
{
    const int idx = blockIdx.x * blockDim.x + threadIdx.x;
    if (idx < B_ * R_) {
        g_h0[idx] = 0.f;
        g_h1[idx] = 0.f;
        g_h1all[idx] = 0.f;  // state entering t=0
    }
}

// ---------------------------------------------------------------
// Decoder head: per row, mean/std/softplus/NLL -> g_rowsum[row]
// ---------------------------------------------------------------
__global__ void __launch_bounds__(128) head_kernel(
    const float* __restrict__ d2base, const float* __restrict__ ybase,
    const float* __restrict__ mw, const float* __restrict__ mb,
    const float* __restrict__ sw, const float* __restrict__ sb,
    float* __restrict__ rowsum)
{
    __shared__ float sd[H_];
    __shared__ float sms[64];
    const int row = blockIdx.x;
    const int tid = threadIdx.x;
    const float* d2 = d2base + (size_t)row * H_;
    for (int i = tid; i < H_; i += 128) sd[i] = d2[i];
    __syncthreads();

    if (tid < 64) {
        const int j = tid & 31;
        const float* w = (tid < 32 ? mw : sw) + (size_t)j * H_;
        float acc = (tid < 32 ? mb[j] : sb[j]);
#pragma unroll 8
        for (int k = 0; k < H_; k++) acc += sd[k] * w[k];
        sms[tid] = acc;
    }
    __syncthreads();

    if (tid < 32) {
        const float mean = sms[tid];
        const float sraw = sms[32 + tid];
        const float stdv = (sraw > 20.f) ? sraw : log1pf(expf(sraw));
        const float yv = ybase[(size_t)row * Y_ + tid];
        const float diff = yv - mean;
        float term = diff * diff / (stdv * stdv) + 2.f * logf(stdv)
                     + 1.8378770664093453f;  // log(2*pi)
#pragma unroll
        for (int o = 16; o > 0; o >>= 1)
            term += __shfl_down_sync(0xffffffffu, term, o);
        if (tid == 0) rowsum[row] = 0.5f * term;
    }
}

// Deterministic final reduction (single block, fixed-order tree, fp64 acc)
__global__ void __launch_bounds__(1024) reduce_kernel(float* __restrict__ out)
{
    __shared__ double sh[1024];
    double s = 0.0;
    for (int i = threadIdx.x; i < T_ * B_; i += 1024)
        s += (double)g_rowsum[i];
    sh[threadIdx.x] = s;
    __syncthreads();
    for (int o = 512; o > 0; o >>= 1) {
        if (threadIdx.x < o) sh[threadIdx.x] += sh[threadIdx.x + o];
        __syncthreads();
    }
    if (threadIdx.x == 0) out[0] = (float)sh[0];
}

// ---------------------------------------------------------------
extern "C" void kernel_launch(void* const* d_in, const int* in_sizes, int n_in,
                              void* d_out, int out_size)
{
    const float* y      = (const float*)d_in[0];
    const float* dec_w1 = (const float*)d_in[1];
    const float* dec_b1 = (const float*)d_in[2];
    const float* dec_w2 = (const float*)d_in[3];
    const float* dec_b2 = (const float*)d_in[4];
    const float* mean_w = (const float*)d_in[5];
    const float* mean_b = (const float*)d_in[6];
    const float* std_w  = (const float*)d_in[7];
    const float* std_b  = (const float*)d_in[8];
    const float* wih0   = (const float*)d_in[9];
    const float* whh0   = (const float*)d_in[10];
    const float* bih0   = (const float*)d_in[11];
    const float* bhh0   = (const float*)d_in[12];
    const float* wih1   = (const float*)d_in[13];
    const float* whh1   = (const float*)d_in[14];
    const float* bih1   = (const float*)d_in[15];
    const float* bhh1   = (const float*)d_in[16];
    float* out = (float*)d_out;

    float *ph1all, *pd1, *pd2, *prow;
    cudaGetSymbolAddress((void**)&ph1all, g_h1all);
    cudaGetSymbolAddress((void**)&pd1, g_d1);
    cudaGetSymbolAddress((void**)&pd2, g_d2);
    cudaGetSymbolAddress((void**)&prow, g_rowsum);

    // 27-node graph: init + persistent scan + 8*(gemm,gemm,head) + reduce
    init_kernel<<<(B_ * R_ + 255) / 256, 256>>>();

    rnn_persistent<<<NBLK_, 256>>>(y, wih0, whh0, bih0, bhh0,
                                   wih1, whh1, bih1, bhh1);

    const dim3 gdec(H_ / 128, ROWS_ / 64);  // (8, 512)
    for (int c = 0; c < NCHUNK_; c++) {
        sgemm_bias_act<<<gdec, 256>>>(ph1all + (size_t)c * ROWS_ * R_,
                                      dec_w1, dec_b1, pd1, ROWS_, H_, R_, 1);
        sgemm_bias_act<<<gdec, 256>>>(pd1, dec_w2, dec_b2, pd2,
                                      ROWS_, H_, H_, 1);
        head_kernel<<<ROWS_, 128>>>(pd2, y + (size_t)c * ROWS_ * Y_,
                                    mean_w, mean_b, std_w, std_b,
                                    prow + (size_t)c * ROWS_);
    }
    reduce_kernel<<<1, 1024>>>(out);
}

// round 9
// speedup vs baseline: 5.7400x; 5.7400x over previous
#include <cuda_runtime.h>
#include <math.h>
#include <stdint.h>

// Problem constants
constexpr int T_ = 256;
constexpr int B_ = 1024;
constexpr int Y_ = 32;
constexpr int H_ = 1024;
constexpr int R_ = 512;
constexpr int R3_ = 3 * R_;          // 1536
constexpr int CHUNK_ = 32;           // timesteps per decoder chunk
constexpr int NCHUNK_ = T_ / CHUNK_; // 8
constexpr int ROWS_ = CHUNK_ * B_;   // 32768 rows per decoder chunk
constexpr int NBLK_ = 296;           // persistent grid: 2 blocks per SM

// -------- device scratch (static: no allocations allowed) --------
__device__ float g_h0[B_ * R_];
__device__ float g_h1[B_ * R_];
__device__ float g_gi[B_ * R3_];
__device__ float g_gh[B_ * R3_];
__device__ float g_gh1[B_ * R3_];
__device__ float g_h1all[(size_t)T_ * B_ * R_];     // h1 entering step t
__device__ float g_d1[(size_t)ROWS_ * H_];          // also reused for mean/std
__device__ float g_d2[(size_t)ROWS_ * H_];
__device__ float g_rowsum[T_ * B_];

// -------- software grid barrier (monotonic generation; replay-safe) ------
__device__ unsigned g_bar_arrive;
__device__ volatile unsigned g_bar_gen;

__device__ __forceinline__ void grid_sync()
{
    __threadfence();
    __syncthreads();
    if (threadIdx.x == 0) {
        unsigned gen = g_bar_gen;
        if (atomicAdd(&g_bar_arrive, 1u) == (unsigned)gridDim.x - 1u) {
            g_bar_arrive = 0u;
            __threadfence();
            g_bar_gen = gen + 1u;
        } else {
            while (g_bar_gen == gen) { __nanosleep(32); }
        }
        __threadfence();
    }
    __syncthreads();
}

// -------- tf32 mma helpers --------
__device__ __forceinline__ uint32_t f2tf(float x)
{
    uint32_t u;
    asm("cvt.rna.tf32.f32 %0, %1;" : "=r"(u) : "f"(x));
    return u;
}

__device__ __forceinline__ void mma_tf32(float* c, uint4 a, uint2 b)
{
    asm volatile(
        "mma.sync.aligned.m16n8k8.row.col.f32.tf32.tf32.f32 "
        "{%0,%1,%2,%3}, {%4,%5,%6,%7}, {%8,%9}, {%0,%1,%2,%3};"
        : "+f"(c[0]), "+f"(c[1]), "+f"(c[2]), "+f"(c[3])
        : "r"(a.x), "r"(a.y), "r"(a.z), "r"(a.w), "r"(b.x), "r"(b.y));
}

// ---------------------------------------------------------------
// Generic tf32 mma block tile: C[BMxBN] = act(A[BM,K] @ W[BN,K]^T + bias)
// BM = WM*MT*16, BN = WN*NT*8; 256 threads (8 warps as WM x WN grid).
// BK = 32 per stage. Smem holds mma-fragment-ready layouts:
//   Af[k8][mtile][lane][4 regs], Bf[k8][ntile][lane][2 regs]
// so compute-side fragment loads are conflict-free LDS.128 / LDS.64.
// BSPLIT: W rows [0,BN/2) from W0/bias0, [BN/2,BN) from W1/bias1 (bn must be 0).
// ---------------------------------------------------------------
template<int MT, int NT, int WM, int WN, bool RELU, bool BSPLIT>
__device__ __forceinline__ void mma_tile(
    const float* __restrict__ A,
    const float* __restrict__ W0, const float* __restrict__ W1,
    const float* __restrict__ b0v, const float* __restrict__ b1v,
    float* __restrict__ C, int ldc, int K, int bm, int bn,
    uint32_t* __restrict__ Af, uint32_t* __restrict__ Bf)
{
    constexpr int BM = WM * MT * 16;
    constexpr int BN = WN * NT * 8;
    constexpr int MTILES = BM / 16;
    constexpr int NTILES = BN / 8;
    constexpr int A_LD = BM * 8 / 256;   // float4 per thread per stage
    constexpr int B_LD = BN * 8 / 256;

    const int tid = threadIdx.x;
    const int lane = tid & 31;
    const int wid = tid >> 5;
    const int wm = wid / WN;
    const int wn = wid % WN;

    float acc[MT][NT][4];
#pragma unroll
    for (int mt = 0; mt < MT; mt++)
#pragma unroll
        for (int nt = 0; nt < NT; nt++)
#pragma unroll
            for (int r = 0; r < 4; r++) acc[mt][nt][r] = 0.f;

    for (int k0 = 0; k0 < K; k0 += 32) {
        __syncthreads();  // previous stage's fragments consumed
        // ---- stage A (BM x 32) into fragment layout ----
#pragma unroll
        for (int i = 0; i < A_LD; i++) {
            const int idx = tid + i * 256;
            const int row = idx >> 3;      // tile-local m
            const int q = idx & 7;         // k quad (4 floats)
            float4 v = *reinterpret_cast<const float4*>(
                A + (size_t)(bm + row) * K + k0 + q * 4);
            const int k8 = q >> 1;
            const int rhi = (q & 1) * 2;   // (k&4) bit -> regs {2,3}
            const int mtile = row >> 4, mlo = row & 15;
            const int r = (mlo >> 3) + rhi;
            uint32_t* p = Af + ((size_t)(k8 * MTILES + mtile) * 32
                                + (mlo & 7) * 4) * 4 + r;
            p[0]  = f2tf(v.x);
            p[4]  = f2tf(v.y);
            p[8]  = f2tf(v.z);
            p[12] = f2tf(v.w);
        }
        // ---- stage W (BN x 32) into fragment layout ----
#pragma unroll
        for (int i = 0; i < B_LD; i++) {
            const int idx = tid + i * 256;
            const int row = idx >> 3;      // tile-local n
            const int q = idx & 7;
            const float* wp;
            if (BSPLIT)
                wp = (row < BN / 2) ? (W0 + (size_t)row * K)
                                    : (W1 + (size_t)(row - BN / 2) * K);
            else
                wp = W0 + (size_t)(bn + row) * K;
            float4 v = *reinterpret_cast<const float4*>(wp + k0 + q * 4);
            const int k8 = q >> 1;
            const int reg = q & 1;         // (k&4) bit
            const int ntile = row >> 3, nlo = row & 7;
            uint32_t* p = Bf + ((size_t)(k8 * NTILES + ntile) * 32
                                + nlo * 4) * 2 + reg;
            p[0] = f2tf(v.x);
            p[2] = f2tf(v.y);
            p[4] = f2tf(v.z);
            p[6] = f2tf(v.w);
        }
        __syncthreads();
        // ---- compute ----
#pragma unroll
        for (int k8 = 0; k8 < 4; k8++) {
            uint4 a[MT];
            uint2 b[NT];
#pragma unroll
            for (int mt = 0; mt < MT; mt++)
                a[mt] = *reinterpret_cast<const uint4*>(
                    Af + ((size_t)(k8 * MTILES + wm * MT + mt) * 32 + lane) * 4);
#pragma unroll
            for (int nt = 0; nt < NT; nt++)
                b[nt] = *reinterpret_cast<const uint2*>(
                    Bf + ((size_t)(k8 * NTILES + wn * NT + nt) * 32 + lane) * 2);
#pragma unroll
            for (int mt = 0; mt < MT; mt++)
#pragma unroll
                for (int nt = 0; nt < NT; nt++)
                    mma_tf32(acc[mt][nt], a[mt], b[nt]);
        }
    }

    // ---- epilogue ----
    const int g = lane >> 2, tig = lane & 3;
#pragma unroll
    for (int mt = 0; mt < MT; mt++) {
#pragma unroll
        for (int nt = 0; nt < NT; nt++) {
            const int row0 = bm + (wm * MT + mt) * 16 + g;
            const int col = (wn * NT + nt) * 8 + 2 * tig;  // tile-local
            float bb0, bb1;
            if (BSPLIT) {
                bb0 = (col < BN / 2) ? b0v[col] : b1v[col - BN / 2];
                bb1 = (col + 1 < BN / 2) ? b0v[col + 1] : b1v[col + 1 - BN / 2];
            } else {
                bb0 = b0v[bn + col];
                bb1 = b0v[bn + col + 1];
            }
            float v00 = acc[mt][nt][0] + bb0, v01 = acc[mt][nt][1] + bb1;
            float v10 = acc[mt][nt][2] + bb0, v11 = acc[mt][nt][3] + bb1;
            if (RELU) {
                v00 = fmaxf(v00, 0.f); v01 = fmaxf(v01, 0.f);
                v10 = fmaxf(v10, 0.f); v11 = fmaxf(v11, 0.f);
            }
            float2* p0 = reinterpret_cast<float2*>(
                C + (size_t)row0 * ldc + bn + col);
            float2* p1 = reinterpret_cast<float2*>(
                C + (size_t)(row0 + 8) * ldc + bn + col);
            *p0 = make_float2(v00, v01);
            *p1 = make_float2(v10, v11);
        }
    }
}

// GRU gate fuse over the full grid (grid-stride): h = (1-z)*n + z*h
__device__ __forceinline__ void gate_phase(
    const float* __restrict__ gi, const float* __restrict__ gh,
    float* __restrict__ h, float* __restrict__ slot)
{
    const int stride = gridDim.x * blockDim.x;
    for (int idx = blockIdx.x * blockDim.x + threadIdx.x;
         idx < B_ * R_; idx += stride) {
        const int b = idx >> 9;
        const int j = idx & (R_ - 1);
        const float* gib = gi + (size_t)b * R3_;
        const float* ghb = gh + (size_t)b * R3_;
        const float ir = gib[j],          hr = ghb[j];
        const float iz = gib[R_ + j],     hz = ghb[R_ + j];
        const float in = gib[2 * R_ + j], hn = ghb[2 * R_ + j];
        const float r = 1.f / (1.f + expf(-(ir + hr)));
        const float z = 1.f / (1.f + expf(-(iz + hz)));
        const float n = tanhf(in + r * hn);
        const float hv = (1.f - z) * n + z * h[idx];
        h[idx] = hv;
        if (slot) slot[idx] = hv;
    }
}

// ---------------------------------------------------------------
// Persistent recurrence: the entire T=256 scan in ONE launch.
// Phase balance: P0 = gh0(96) + gh1-first-half(48) + gi0(96, K=32) = 240 tiles
//                P2 = gi1(96) + gh1-second-half(48)                = 144 tiles
// so every SM has at most ~1 heavy tile per phase.
// ---------------------------------------------------------------
__global__ void __launch_bounds__(256, 2) rnn_persistent(
    const float* __restrict__ y,
    const float* __restrict__ wih0, const float* __restrict__ whh0,
    const float* __restrict__ bih0, const float* __restrict__ bhh0,
    const float* __restrict__ wih1, const float* __restrict__ whh1,
    const float* __restrict__ bih1, const float* __restrict__ bhh1)
{
    __shared__ uint32_t Af[4096];
    __shared__ uint32_t Bf[4096];
    const int bid = blockIdx.x;

    for (int t = 0; t < T_; t++) {
        const float* y_t = y + (size_t)t * B_ * Y_;

        // ---- P0 ----
        if (bid < 240) {
            const float *Ap, *Wp, *bp;
            float* Cp;
            int Kv, tt;
            if (bid < 96)       { tt = bid;       Ap = g_h0; Wp = whh0; bp = bhh0; Cp = g_gh;  Kv = R_; }
            else if (bid < 144) { tt = bid - 96;  Ap = g_h1; Wp = whh1; bp = bhh1; Cp = g_gh1; Kv = R_; }
            else                { tt = bid - 144; Ap = y_t;  Wp = wih0; bp = bih0; Cp = g_gi;  Kv = Y_; }
            const int bm = (tt / 12) * 128;
            const int bn = (tt % 12) * 128;
            mma_tile<4, 4, 2, 4, false, false>(Ap, Wp, nullptr, bp, nullptr,
                                               Cp, R3_, Kv, bm, bn, Af, Bf);
        }
        grid_sync();

        // ---- P1: gate layer 0 -> new h0 ----
        gate_phase(g_gi, g_gh, g_h0, nullptr);
        grid_sync();

        // ---- P2 ----
        if (bid < 144) {
            const float *Ap, *Wp, *bp;
            float* Cp;
            int tt;
            if (bid < 96) { tt = bid;            Ap = g_h0; Wp = wih1; bp = bih1; Cp = g_gi;  }
            else          { tt = bid - 96 + 48;  Ap = g_h1; Wp = whh1; bp = bhh1; Cp = g_gh1; }
            const int bm = (tt / 12) * 128;
            const int bn = (tt % 12) * 128;
            mma_tile<4, 4, 2, 4, false, false>(Ap, Wp, nullptr, bp, nullptr,
                                               Cp, R3_, R_, bm, bn, Af, Bf);
        }
        grid_sync();

        // ---- P3: gate layer 1 -> new h1 (+ record state entering t+1) ----
        float* slot = (t + 1 < T_) ? (g_h1all + (size_t)(t + 1) * B_ * R_)
                                   : nullptr;
        gate_phase(g_gi, g_gh1, g_h1, slot);
        grid_sync();
    }
}

// ---------------------------------------------------------------
// Decoder GEMM: C = relu(A @ W^T + b), 128x128 tiles, N = H_ fixed.
// ---------------------------------------------------------------
__global__ void __launch_bounds__(256, 2) dec_gemm(
    const float* __restrict__ A, const float* __restrict__ W,
    const float* __restrict__ bias, float* __restrict__ C, int K)
{
    __shared__ uint32_t Af[4096];
    __shared__ uint32_t Bf[4096];
    const int bm = blockIdx.y * 128;
    const int bn = blockIdx.x * 128;
    mma_tile<4, 4, 2, 4, true, false>(A, W, nullptr, bias, nullptr,
                                      C, H_, K, bm, bn, Af, Bf);
}

// ---------------------------------------------------------------
// Head GEMM: ms[row][0..31] = d2@mean_w^T + mb, ms[row][32..63] = d2@std_w^T + sb
// 128x64 tiles (warp tile 32x32), K = H_.
// ---------------------------------------------------------------
__global__ void __launch_bounds__(256, 2) head_gemm(
    const float* __restrict__ d2,
    const float* __restrict__ mw, const float* __restrict__ sw,
    const float* __restrict__ mb, const float* __restrict__ sb,
    float* __restrict__ ms)
{
    __shared__ uint32_t Af[4096];
    __shared__ uint32_t Bf[2048];
    const int bm = blockIdx.x * 128;
    mma_tile<2, 4, 4, 2, false, true>(d2, mw, sw, mb, sb,
                                      ms, 64, H_, bm, 0, Af, Bf);
}

// NLL per row from mean/std: one warp per row.
__global__ void __launch_bounds__(256) nll_kernel(
    const float* __restrict__ ms, const float* __restrict__ ybase,
    float* __restrict__ rowsum)
{
    const int row = blockIdx.x * 8 + (threadIdx.x >> 5);
    const int lane = threadIdx.x & 31;
    const float* m = ms + (size_t)row * 64;
    const float mean = m[lane];
    const float sraw = m[32 + lane];
    const float stdv = (sraw > 20.f) ? sraw : log1pf(expf(sraw));
    const float yv = ybase[(size_t)row * Y_ + lane];
    const float diff = yv - mean;
    float term = diff * diff / (stdv * stdv) + 2.f * logf(stdv)
                 + 1.8378770664093453f;  // log(2*pi)
#pragma unroll
    for (int o = 16; o > 0; o >>= 1)
        term += __shfl_down_sync(0xffffffffu, term, o);
    if (lane == 0) rowsum[row] = 0.5f * term;
}

// ---------------------------------------------------------------
__global__ void init_kernel()
{
    const int idx = blockIdx.x * blockDim.x + threadIdx.x;
    if (idx < B_ * R_) {
        g_h0[idx] = 0.f;
        g_h1[idx] = 0.f;
        g_h1all[idx] = 0.f;  // state entering t=0
    }
}

// Deterministic final reduction (single block, fixed-order tree, fp64 acc)
__global__ void __launch_bounds__(1024) reduce_kernel(float* __restrict__ out)
{
    __shared__ double sh[1024];
    double s = 0.0;
    for (int i = threadIdx.x; i < T_ * B_; i += 1024)
        s += (double)g_rowsum[i];
    sh[threadIdx.x] = s;
    __syncthreads();
    for (int o = 512; o > 0; o >>= 1) {
        if (threadIdx.x < o) sh[threadIdx.x] += sh[threadIdx.x + o];
        __syncthreads();
    }
    if (threadIdx.x == 0) out[0] = (float)sh[0];
}

// ---------------------------------------------------------------
extern "C" void kernel_launch(void* const* d_in, const int* in_sizes, int n_in,
                              void* d_out, int out_size)
{
    const float* y      = (const float*)d_in[0];
    const float* dec_w1 = (const float*)d_in[1];
    const float* dec_b1 = (const float*)d_in[2];
    const float* dec_w2 = (const float*)d_in[3];
    const float* dec_b2 = (const float*)d_in[4];
    const float* mean_w = (const float*)d_in[5];
    const float* mean_b = (const float*)d_in[6];
    const float* std_w  = (const float*)d_in[7];
    const float* std_b  = (const float*)d_in[8];
    const float* wih0   = (const float*)d_in[9];
    const float* whh0   = (const float*)d_in[10];
    const float* bih0   = (const float*)d_in[11];
    const float* bhh0   = (const float*)d_in[12];
    const float* wih1   = (const float*)d_in[13];
    const float* whh1   = (const float*)d_in[14];
    const float* bih1   = (const float*)d_in[15];
    const float* bhh1   = (const float*)d_in[16];
    float* out = (float*)d_out;

    float *ph1all, *pd1, *pd2, *prow;
    cudaGetSymbolAddress((void**)&ph1all, g_h1all);
    cudaGetSymbolAddress((void**)&pd1, g_d1);
    cudaGetSymbolAddress((void**)&pd2, g_d2);
    cudaGetSymbolAddress((void**)&prow, g_rowsum);

    // 35-node graph
    init_kernel<<<(B_ * R_ + 255) / 256, 256>>>();

    rnn_persistent<<<NBLK_, 256>>>(y, wih0, whh0, bih0, bhh0,
                                   wih1, whh1, bih1, bhh1);

    const dim3 gdec(H_ / 128, ROWS_ / 128);  // (8, 256)
    for (int c = 0; c < NCHUNK_; c++) {
        dec_gemm<<<gdec, 256>>>(ph1all + (size_t)c * ROWS_ * R_,
                                dec_w1, dec_b1, pd1, R_);
        dec_gemm<<<gdec, 256>>>(pd1, dec_w2, dec_b2, pd2, H_);
        head_gemm<<<ROWS_ / 128, 256>>>(pd2, mean_w, std_w, mean_b, std_b,
                                        pd1);  // d1 reused as [ROWS][64]
        nll_kernel<<<ROWS_ / 8, 256>>>(pd1, y + (size_t)c * ROWS_ * Y_,
                                       prow + (size_t)c * ROWS_);
    }
    reduce_kernel<<<1, 1024>>>(out);
}

// round 10
// speedup vs baseline: 7.3225x; 1.2757x over previous
#include <cuda_runtime.h>
#include <math.h>
#include <stdint.h>

// Problem constants
constexpr int T_ = 256;
constexpr int B_ = 1024;
constexpr int Y_ = 32;
constexpr int H_ = 1024;
constexpr int R_ = 512;
constexpr int R3_ = 3 * R_;          // 1536
constexpr int CHUNK_ = 32;
constexpr int NCHUNK_ = T_ / CHUNK_; // 8
constexpr int ROWS_ = CHUNK_ * B_;   // 32768
constexpr int NBLK_ = 296;           // persistent grid: 2 blocks per SM

// ---------------- device scratch (static; no allocations) ----------------
__device__ float    g_h0[B_ * R_];
__device__ float    g_h1[B_ * R_];
__device__ uint32_t g_h0f[B_ * R_ / 2];             // bf16 frag copy of h0
__device__ uint32_t g_h1f[B_ * R_ / 2];
__device__ uint32_t g_yf[(size_t)T_ * B_ * Y_ / 2]; // y in bf16 frag order
__device__ float    g_gi[B_ * R3_];
__device__ float    g_gh[B_ * R3_];
__device__ float    g_gh1[B_ * R3_];
__device__ uint32_t g_h1allf[(size_t)T_ * B_ * R_ / 2];  // 256 MB
__device__ uint32_t g_d1f[(size_t)ROWS_ * H_ / 2];       // 64 MB
__device__ uint32_t g_d2f[(size_t)ROWS_ * H_ / 2];
__device__ float    g_ms[(size_t)ROWS_ * 64];
__device__ float    g_rowsum[T_ * B_];
// prepacked bf16 weights (B-fragment order)
__device__ uint32_t g_whh0f[R3_ * R_ / 2];
__device__ uint32_t g_wih0f[R3_ * Y_ / 2];
__device__ uint32_t g_wih1f[R3_ * R_ / 2];
__device__ uint32_t g_whh1f[R3_ * R_ / 2];
__device__ uint32_t g_w1f[H_ * R_ / 2];
__device__ uint32_t g_w2f[H_ * H_ / 2];
__device__ uint32_t g_mswf[64 * H_ / 2];   // mean rows (ntiles 0..3) + std rows (4..7)

// ---------------- software grid barrier (replay-safe) ----------------
__device__ unsigned g_bar_arrive;
__device__ volatile unsigned g_bar_gen;

__device__ __forceinline__ void grid_sync()
{
    __threadfence();
    __syncthreads();
    if (threadIdx.x == 0) {
        unsigned gen = g_bar_gen;
        if (atomicAdd(&g_bar_arrive, 1u) == (unsigned)gridDim.x - 1u) {
            g_bar_arrive = 0u;
            __threadfence();
            g_bar_gen = gen + 1u;
        } else {
            while (g_bar_gen == gen) { __nanosleep(32); }
        }
        __threadfence();
    }
    __syncthreads();
}

// ---------------- bf16 helpers ----------------
// pack two fp32 -> bf16x2 word; LOWER half = lo (lower-k element)
__device__ __forceinline__ uint32_t packbf(float lo, float hi)
{
    uint32_t u;
    asm("cvt.rn.bf16x2.f32 %0, %1, %2;" : "=r"(u) : "f"(hi), "f"(lo));
    return u;
}

__device__ __forceinline__ void mma_bf16(float* c, const uint32_t* a, uint2 b)
{
    asm volatile(
        "mma.sync.aligned.m16n8k16.row.col.f32.bf16.bf16.f32 "
        "{%0,%1,%2,%3}, {%4,%5,%6,%7}, {%8,%9}, {%0,%1,%2,%3};"
        : "+f"(c[0]), "+f"(c[1]), "+f"(c[2]), "+f"(c[3])
        : "r"(a[0]), "r"(a[1]), "r"(a[2]), "r"(a[3]), "r"(b.x), "r"(b.y));
}

// ---------------------------------------------------------------
// Fragment layouts (bf16x2 words):
//  A matrix [M x K]: block (mtile=m>>4, k16=k>>4), blocks mtile-major:
//    word = (mtile*(K/16)+k16)*128 + r*32 + (m&7)*4 + ((k>>1)&3)
//    r = ((m>>3)&1) + 2*((k>>3)&1)
//  B (weights) [N x K]: block (ntile=n>>3, k16):
//    word = (ntile*(K/16)+k16)*64 + ((n&7)*4 + ((k>>1)&3))*2 + ((k>>3)&1)
//    -> per-lane LDG.64 gives {b0,b1} directly.
// ---------------------------------------------------------------
// bf16 mma block tile, BM=128, BN=WN*NT*8, 256 threads (WM x WN warps).
// A from fragment-order global via double-buffered smem memcpy (SK k16's
// per stage); B direct from L2 (prepacked). OUTMODE: 0 = fp32 C (+bias),
// 1 = fp32 C with split bias (head), 2 = bf16-frag output with ReLU.
template<int MT, int NT, int WM, int WN, int SK, int OUTMODE>
__device__ __forceinline__ void mma_tile_bf16(
    const uint32_t* __restrict__ Af, const uint32_t* __restrict__ Bf,
    const float* __restrict__ b0v, const float* __restrict__ b1v,
    float* __restrict__ C, int ldc,
    uint32_t* __restrict__ Of, int o_nk16,
    int K, int bm, int bn, uint32_t* __restrict__ Asm)
{
    const int NK16 = K / 16;
    const int S = NK16 / SK;
    const int tid = threadIdx.x;
    const int lane = tid & 31;
    const int wid = tid >> 5;
    const int wm = wid / WN, wn = wid % WN;
    const int bn8 = bn >> 3;
    const int mtile0 = bm >> 4;

    float acc[MT][NT][4];
#pragma unroll
    for (int mt = 0; mt < MT; mt++)
#pragma unroll
        for (int nt = 0; nt < NT; nt++)
#pragma unroll
            for (int r = 0; r < 4; r++) acc[mt][nt][r] = 0.f;

    // prologue: stage 0 -> smem buffer 0
    {
        uint4 st[SK];
#pragma unroll
        for (int j = 0; j < SK; j++) {
            const int u = j * 256 + tid;
            const int blk = u >> 5, off = u & 31;
            const int mt = blk & 7, kl = blk >> 3;
            st[j] = *reinterpret_cast<const uint4*>(
                Af + ((size_t)(mtile0 + mt) * NK16 + kl) * 128 + off * 4);
        }
#pragma unroll
        for (int j = 0; j < SK; j++)
            reinterpret_cast<uint4*>(Asm)[j * 256 + tid] = st[j];
    }
    __syncthreads();

    for (int s = 0; s < S; s++) {
        uint32_t* cbuf = Asm + (s & 1) * (SK * 1024);
        uint32_t* nbuf = Asm + ((s + 1) & 1) * (SK * 1024);
        uint4 nx[SK];
        if (s + 1 < S) {
#pragma unroll
            for (int j = 0; j < SK; j++) {
                const int u = j * 256 + tid;
                const int blk = u >> 5, off = u & 31;
                const int mt = blk & 7, kl = blk >> 3;
                nx[j] = *reinterpret_cast<const uint4*>(
                    Af + ((size_t)(mtile0 + mt) * NK16 + (s + 1) * SK + kl) * 128
                       + off * 4);
            }
        }
#pragma unroll
        for (int kl = 0; kl < SK; kl++) {
            const int k16 = s * SK + kl;
            uint2 bfr[NT];
#pragma unroll
            for (int nt = 0; nt < NT; nt++)
                bfr[nt] = *reinterpret_cast<const uint2*>(
                    Bf + ((size_t)(bn8 + wn * NT + nt) * NK16 + k16) * 64
                       + lane * 2);
            uint32_t afr[MT][4];
#pragma unroll
            for (int mt = 0; mt < MT; mt++)
#pragma unroll
                for (int r = 0; r < 4; r++)
                    afr[mt][r] = cbuf[(kl * 8 + wm * MT + mt) * 128 + r * 32 + lane];
#pragma unroll
            for (int mt = 0; mt < MT; mt++)
#pragma unroll
                for (int nt = 0; nt < NT; nt++)
                    mma_bf16(acc[mt][nt], afr[mt], bfr[nt]);
        }
        if (s + 1 < S) {
#pragma unroll
            for (int j = 0; j < SK; j++)
                reinterpret_cast<uint4*>(nbuf)[j * 256 + tid] = nx[j];
        }
        __syncthreads();
    }

    // epilogue
    const int g = lane >> 2, tig = lane & 3;
#pragma unroll
    for (int mt = 0; mt < MT; mt++) {
#pragma unroll
        for (int nt = 0; nt < NT; nt++) {
            const int m0 = bm + (wm * MT + mt) * 16 + g;
            const int col = (wn * NT + nt) * 8 + 2 * tig;   // tile-local
            float bb0, bb1;
            if (OUTMODE == 1) {
                bb0 = (col < 32) ? b0v[col] : b1v[col - 32];
                bb1 = (col + 1 < 32) ? b0v[col + 1] : b1v[col + 1 - 32];
            } else {
                bb0 = b0v[bn + col];
                bb1 = b0v[bn + col + 1];
            }
            float v00 = acc[mt][nt][0] + bb0, v01 = acc[mt][nt][1] + bb1;
            float v10 = acc[mt][nt][2] + bb0, v11 = acc[mt][nt][3] + bb1;
            if (OUTMODE == 2) {
                v00 = fmaxf(v00, 0.f); v01 = fmaxf(v01, 0.f);
                v10 = fmaxf(v10, 0.f); v11 = fmaxf(v11, 0.f);
                const int kc = bn + col;
                const size_t w = ((size_t)(m0 >> 4) * o_nk16 + (kc >> 4)) * 128
                                 + ((kc >> 3) & 1) * 64 + (m0 & 7) * 4 + tig;
                Of[w]      = packbf(v00, v01);   // rows m0   (r = 2*kb)
                Of[w + 32] = packbf(v10, v11);   // rows m0+8 (r = 2*kb+1)
            } else {
                *reinterpret_cast<float2*>(C + (size_t)m0 * ldc + bn + col) =
                    make_float2(v00, v01);
                *reinterpret_cast<float2*>(C + (size_t)(m0 + 8) * ldc + bn + col) =
                    make_float2(v10, v11);
            }
        }
    }
}

// ---------------------------------------------------------------
// GRU gate fuse: 8 elements per thread; writes fp32 h + bf16 fragment word.
// NOTE: no early return (persistent kernel has grid_syncs after this).
// ---------------------------------------------------------------
__device__ __forceinline__ void gate_phase(
    const float* __restrict__ gi, const float* __restrict__ gh,
    float* __restrict__ h, uint32_t* __restrict__ hf,
    uint32_t* __restrict__ slotf)
{
    const int idx = blockIdx.x * blockDim.x + threadIdx.x;
    if (idx < B_ * R_ / 8) {
        const int b = idx >> 6, jb = idx & 63, j0 = jb << 3;
        const float* gib = gi + (size_t)b * R3_ + j0;
        const float* ghb = gh + (size_t)b * R3_ + j0;
        float* hb = h + (size_t)b * R_ + j0;
        float ir[8], iz[8], in_[8], hr[8], hz[8], hn[8], ho[8], hv[8];
        *(float4*)(ir)      = *(const float4*)(gib);
        *(float4*)(ir + 4)  = *(const float4*)(gib + 4);
        *(float4*)(iz)      = *(const float4*)(gib + R_);
        *(float4*)(iz + 4)  = *(const float4*)(gib + R_ + 4);
        *(float4*)(in_)     = *(const float4*)(gib + 2 * R_);
        *(float4*)(in_ + 4) = *(const float4*)(gib + 2 * R_ + 4);
        *(float4*)(hr)      = *(const float4*)(ghb);
        *(float4*)(hr + 4)  = *(const float4*)(ghb + 4);
        *(float4*)(hz)      = *(const float4*)(ghb + R_);
        *(float4*)(hz + 4)  = *(const float4*)(ghb + R_ + 4);
        *(float4*)(hn)      = *(const float4*)(ghb + 2 * R_);
        *(float4*)(hn + 4)  = *(const float4*)(ghb + 2 * R_ + 4);
        *(float4*)(ho)      = *(const float4*)(hb);
        *(float4*)(ho + 4)  = *(const float4*)(hb + 4);
#pragma unroll
        for (int i = 0; i < 8; i++) {
            const float r = 1.f / (1.f + expf(-(ir[i] + hr[i])));
            const float z = 1.f / (1.f + expf(-(iz[i] + hz[i])));
            const float n = tanhf(in_[i] + r * hn[i]);
            hv[i] = (1.f - z) * n + z * ho[i];
        }
        *(float4*)(hb)     = make_float4(hv[0], hv[1], hv[2], hv[3]);
        *(float4*)(hb + 4) = make_float4(hv[4], hv[5], hv[6], hv[7]);
        uint4 pk = make_uint4(packbf(hv[0], hv[1]), packbf(hv[2], hv[3]),
                              packbf(hv[4], hv[5]), packbf(hv[6], hv[7]));
        // fragment word/4: blk=(b>>4)*32+(jb>>1); r=((b>>3)&1)+2*(jb&1)
        const size_t w4 = ((size_t)(b >> 4) * 32 + (jb >> 1)) * 32
                          + (((b >> 3) & 1) + 2 * (jb & 1)) * 8 + (b & 7);
        reinterpret_cast<uint4*>(hf)[w4] = pk;
        if (slotf) reinterpret_cast<uint4*>(slotf)[w4] = pk;
    }
}

// ---------------------------------------------------------------
// Persistent recurrence: whole T=256 scan in one launch.
// P0 = gh0(96) + gh1(96) + gi0(96,K=32) = 288 tiles; P2 = gi1(96).
// ---------------------------------------------------------------
__global__ void __launch_bounds__(256, 2) rnn_persistent(
    const float* __restrict__ bih0, const float* __restrict__ bhh0,
    const float* __restrict__ bih1, const float* __restrict__ bhh1)
{
    __shared__ uint32_t Asm[2 * 4 * 1024];   // 32 KB
    const int bid = blockIdx.x;

    for (int t = 0; t < T_; t++) {
        // ---- P0 ----
        if (bid < 288) {
            const int grp = bid / 96, tt = bid % 96;
            const int bm = (tt / 12) * 128;
            const int bn = (tt % 12) * 128;
            if (grp == 0)
                mma_tile_bf16<4, 4, 2, 4, 4, 0>(g_h0f, g_whh0f, bhh0, nullptr,
                    g_gh, R3_, nullptr, 0, R_, bm, bn, Asm);
            else if (grp == 1)
                mma_tile_bf16<4, 4, 2, 4, 4, 0>(g_h1f, g_whh1f, bhh1, nullptr,
                    g_gh1, R3_, nullptr, 0, R_, bm, bn, Asm);
            else
                mma_tile_bf16<4, 4, 2, 4, 2, 0>(g_yf + (size_t)t * (B_ * Y_ / 2),
                    g_wih0f, bih0, nullptr, g_gi, R3_, nullptr, 0, Y_, bm, bn, Asm);
        }
        grid_sync();

        // ---- P1: gate layer 0 -> new h0 (fp32 + frag) ----
        gate_phase(g_gi, g_gh, g_h0, g_h0f, nullptr);
        grid_sync();

        // ---- P2: gi1 = h0' @ wih1^T ----
        if (bid < 96) {
            const int bm = (bid / 12) * 128;
            const int bn = (bid % 12) * 128;
            mma_tile_bf16<4, 4, 2, 4, 4, 0>(g_h0f, g_wih1f, bih1, nullptr,
                g_gi, R3_, nullptr, 0, R_, bm, bn, Asm);
        }
        grid_sync();

        // ---- P3: gate layer 1 -> new h1 (+ h1all slot t+1) ----
        uint32_t* slot = (t + 1 < T_)
            ? (g_h1allf + (size_t)(t + 1) * (B_ * R_ / 2)) : nullptr;
        gate_phase(g_gi, g_gh1, g_h1, g_h1f, slot);
        grid_sync();
    }
}

// ---------------------------------------------------------------
// Decoder GEMM: frag-A @ prepacked-W -> frag output, ReLU. 128x128 tiles.
__global__ void __launch_bounds__(256, 2) dec_gemm(
    const uint32_t* __restrict__ Af, const uint32_t* __restrict__ Bf,
    const float* __restrict__ bias, uint32_t* __restrict__ Of, int K)
{
    __shared__ uint32_t Asm[2 * 4 * 1024];
    const int bm = blockIdx.y * 128;
    const int bn = blockIdx.x * 128;
    mma_tile_bf16<4, 4, 2, 4, 4, 2>(Af, Bf, bias, nullptr, nullptr, 0,
                                    Of, H_ / 16, K, bm, bn, Asm);
}

// Head GEMM: d2f @ [mean_w; std_w] -> ms fp32 [rows][64]. 128x64 tiles.
__global__ void __launch_bounds__(256, 2) head_gemm(
    const uint32_t* __restrict__ d2f, const uint32_t* __restrict__ mswf,
    const float* __restrict__ mb, const float* __restrict__ sb,
    float* __restrict__ ms)
{
    __shared__ uint32_t Asm[2 * 4 * 1024];
    const int bm = blockIdx.x * 128;
    mma_tile_bf16<2, 4, 4, 2, 4, 1>(d2f, mswf, mb, sb, ms, 64,
                                    nullptr, 0, H_, bm, 0, Asm);
}

// NLL per row: one warp per row, reads ms fp32.
__global__ void __launch_bounds__(256) nll_kernel(
    const float* __restrict__ ms, const float* __restrict__ ybase,
    float* __restrict__ rowsum)
{
    const int row = blockIdx.x * 8 + (threadIdx.x >> 5);
    const int lane = threadIdx.x & 31;
    const float* m = ms + (size_t)row * 64;
    const float mean = m[lane];
    const float sraw = m[32 + lane];
    const float stdv = (sraw > 20.f) ? sraw : log1pf(expf(sraw));
    const float yv = ybase[(size_t)row * Y_ + lane];
    const float diff = yv - mean;
    float term = diff * diff / (stdv * stdv) + 2.f * logf(stdv)
                 + 1.8378770664093453f;  // log(2*pi)
#pragma unroll
    for (int o = 16; o > 0; o >>= 1)
        term += __shfl_down_sync(0xffffffffu, term, o);
    if (lane == 0) rowsum[row] = 0.5f * term;
}

// ---------------------------------------------------------------
// Weight prepack: W[N x K] fp32 -> bf16 B-fragment order.
__global__ void prepack_w(const float* __restrict__ W, uint32_t* __restrict__ out,
                          int N, int K)
{
    const int idx = blockIdx.x * blockDim.x + threadIdx.x;
    if (idx >= N * K / 2) return;
    const int n = idx / (K / 2), p = idx % (K / 2);
    const int k = p * 2;
    const uint32_t w = packbf(W[(size_t)n * K + k], W[(size_t)n * K + k + 1]);
    const int ntile = n >> 3, g = n & 7;
    const int tig = p & 3, reg = (p >> 2) & 1, k16 = p >> 3;
    out[((size_t)ntile * (K / 16) + k16) * 64 + (g * 4 + tig) * 2 + reg] = w;
}

// y prepack: y[T][B][Y] fp32 -> per-t A-fragment order bf16.
__global__ void prepack_y(const float* __restrict__ y, uint32_t* __restrict__ out)
{
    const int idx = blockIdx.x * blockDim.x + threadIdx.x;
    if (idx >= T_ * B_ * Y_ / 2) return;
    const int p = idx & 15, b = (idx >> 4) & 1023, t = idx >> 14;
    const int k = p * 2;
    const float* yp = y + ((size_t)t * B_ + b) * Y_ + k;
    const uint32_t w = packbf(yp[0], yp[1]);
    const int k16 = p >> 3, kb = (p >> 2) & 1, tig = p & 3;
    const int r = ((b >> 3) & 1) + 2 * kb;
    const size_t word = (((size_t)t * 64 + (b >> 4)) * 2 + k16) * 128
                        + r * 32 + (b & 7) * 4 + tig;
    out[word] = w;
}

// init: zero states (fp32 + frag) and h1all slot 0.
__global__ void init_kernel()
{
    const int idx = blockIdx.x * blockDim.x + threadIdx.x;
    if (idx < B_ * R_) {
        g_h0[idx] = 0.f;
        g_h1[idx] = 0.f;
    }
    if (idx < B_ * R_ / 2) {
        g_h0f[idx] = 0u;
        g_h1f[idx] = 0u;
        g_h1allf[idx] = 0u;
    }
}

// Deterministic final reduction (fixed-order tree, fp64 accumulate)
__global__ void __launch_bounds__(1024) reduce_kernel(float* __restrict__ out)
{
    __shared__ double sh[1024];
    double s = 0.0;
    for (int i = threadIdx.x; i < T_ * B_; i += 1024)
        s += (double)g_rowsum[i];
    sh[threadIdx.x] = s;
    __syncthreads();
    for (int o = 512; o > 0; o >>= 1) {
        if (threadIdx.x < o) sh[threadIdx.x] += sh[threadIdx.x + o];
        __syncthreads();
    }
    if (threadIdx.x == 0) out[0] = (float)sh[0];
}

// ---------------------------------------------------------------
extern "C" void kernel_launch(void* const* d_in, const int* in_sizes, int n_in,
                              void* d_out, int out_size)
{
    const float* y      = (const float*)d_in[0];
    const float* dec_w1 = (const float*)d_in[1];
    const float* dec_b1 = (const float*)d_in[2];
    const float* dec_w2 = (const float*)d_in[3];
    const float* dec_b2 = (const float*)d_in[4];
    const float* mean_w = (const float*)d_in[5];
    const float* mean_b = (const float*)d_in[6];
    const float* std_w  = (const float*)d_in[7];
    const float* std_b  = (const float*)d_in[8];
    const float* wih0   = (const float*)d_in[9];
    const float* whh0   = (const float*)d_in[10];
    const float* bih0   = (const float*)d_in[11];
    const float* bhh0   = (const float*)d_in[12];
    const float* wih1   = (const float*)d_in[13];
    const float* whh1   = (const float*)d_in[14];
    const float* bih1   = (const float*)d_in[15];
    const float* bhh1   = (const float*)d_in[16];
    float* out = (float*)d_out;

    uint32_t *pwhh0f, *pwih0f, *pwih1f, *pwhh1f, *pw1f, *pw2f, *pmswf;
    uint32_t *pyf, *ph1allf, *pd1f, *pd2f;
    float *pms, *prow;
    cudaGetSymbolAddress((void**)&pwhh0f, g_whh0f);
    cudaGetSymbolAddress((void**)&pwih0f, g_wih0f);
    cudaGetSymbolAddress((void**)&pwih1f, g_wih1f);
    cudaGetSymbolAddress((void**)&pwhh1f, g_whh1f);
    cudaGetSymbolAddress((void**)&pw1f, g_w1f);
    cudaGetSymbolAddress((void**)&pw2f, g_w2f);
    cudaGetSymbolAddress((void**)&pmswf, g_mswf);
    cudaGetSymbolAddress((void**)&pyf, g_yf);
    cudaGetSymbolAddress((void**)&ph1allf, g_h1allf);
    cudaGetSymbolAddress((void**)&pd1f, g_d1f);
    cudaGetSymbolAddress((void**)&pd2f, g_d2f);
    cudaGetSymbolAddress((void**)&pms, g_ms);
    cudaGetSymbolAddress((void**)&prow, g_rowsum);

    // ---- prepacks (run each replay; ~100 us total) ----
    auto blocks = [](int n) { return (n + 255) / 256; };
    prepack_w<<<blocks(R3_ * R_ / 2), 256>>>(whh0, pwhh0f, R3_, R_);
    prepack_w<<<blocks(R3_ * Y_ / 2), 256>>>(wih0, pwih0f, R3_, Y_);
    prepack_w<<<blocks(R3_ * R_ / 2), 256>>>(wih1, pwih1f, R3_, R_);
    prepack_w<<<blocks(R3_ * R_ / 2), 256>>>(whh1, pwhh1f, R3_, R_);
    prepack_w<<<blocks(H_ * R_ / 2), 256>>>(dec_w1, pw1f, H_, R_);
    prepack_w<<<blocks(H_ * H_ / 2), 256>>>(dec_w2, pw2f, H_, H_);
    prepack_w<<<blocks(32 * H_ / 2), 256>>>(mean_w, pmswf, 32, H_);
    prepack_w<<<blocks(32 * H_ / 2), 256>>>(std_w, pmswf + 4 * (H_ / 16) * 64, 32, H_);
    prepack_y<<<blocks(T_ * B_ * Y_ / 2), 256>>>(y, pyf);
    init_kernel<<<blocks(B_ * R_), 256>>>();

    // ---- sequential scan (one persistent kernel) ----
    rnn_persistent<<<NBLK_, 256>>>(bih0, bhh0, bih1, bhh1);

    // ---- decoder + NLL (big parallel GEMMs, chunked) ----
    const dim3 gdec(H_ / 128, ROWS_ / 128);  // (8, 256)
    for (int c = 0; c < NCHUNK_; c++) {
        dec_gemm<<<gdec, 256>>>(ph1allf + (size_t)c * (ROWS_ * R_ / 2),
                                pw1f, dec_b1, pd1f, R_);
        dec_gemm<<<gdec, 256>>>(pd1f, pw2f, dec_b2, pd2f, H_);
        head_gemm<<<ROWS_ / 128, 256>>>(pd2f, pmswf, mean_b, std_b, pms);
        nll_kernel<<<ROWS_ / 8, 256>>>(pms, y + (size_t)c * ROWS_ * Y_,
                                       prow + (size_t)c * ROWS_);
    }
    reduce_kernel<<<1, 1024>>>(out);
}

// round 11
// speedup vs baseline: 10.8096x; 1.4762x over previous
#include <cuda_runtime.h>
#include <math.h>
#include <stdint.h>

// Problem constants
constexpr int T_ = 256;
constexpr int B_ = 1024;
constexpr int Y_ = 32;
constexpr int H_ = 1024;
constexpr int R_ = 512;
constexpr int R3_ = 3 * R_;          // 1536
constexpr int CHUNK_ = 32;
constexpr int NCHUNK_ = T_ / CHUNK_; // 8
constexpr int ROWS_ = CHUNK_ * B_;   // 32768
constexpr int NBLK_ = 296;           // persistent grid: 2 blocks per SM

// ---------------- device scratch (static; no allocations) ----------------
__device__ float    g_h0[B_ * R_];
__device__ float    g_h1[B_ * R_];
__device__ uint32_t g_h0f[B_ * R_ / 2];             // bf16 frag copy of h0
__device__ uint32_t g_h1f[B_ * R_ / 2];
__device__ uint32_t g_yf[(size_t)T_ * B_ * Y_ / 2]; // y in bf16 frag order
__device__ float    g_gi[B_ * R3_];
__device__ float    g_gh[B_ * R3_];
__device__ float    g_gh1[B_ * R3_];
__device__ uint32_t g_h1allf[(size_t)T_ * B_ * R_ / 2];  // 256 MB
__device__ uint32_t g_d1f[(size_t)ROWS_ * H_ / 2];       // 64 MB
__device__ uint32_t g_d2f[(size_t)ROWS_ * H_ / 2];
__device__ float    g_ms[(size_t)ROWS_ * 64];
__device__ float    g_rowsum[T_ * B_];
// prepacked bf16 weights (B-fragment order)
__device__ uint32_t g_whh0f[R3_ * R_ / 2];
__device__ uint32_t g_wih0f[R3_ * Y_ / 2];
__device__ uint32_t g_wih1f[R3_ * R_ / 2];
__device__ uint32_t g_whh1f[R3_ * R_ / 2];
__device__ uint32_t g_w1f[H_ * R_ / 2];
__device__ uint32_t g_w2f[H_ * H_ / 2];
__device__ uint32_t g_mswf[64 * H_ / 2];   // mean rows (ntiles 0..3) + std rows (4..7)

// ---------------- software grid barrier (replay-safe) ----------------
__device__ unsigned g_bar_arrive;
__device__ volatile unsigned g_bar_gen;

__device__ __forceinline__ void grid_sync()
{
    __threadfence();
    __syncthreads();
    if (threadIdx.x == 0) {
        unsigned gen = g_bar_gen;
        if (atomicAdd(&g_bar_arrive, 1u) == (unsigned)gridDim.x - 1u) {
            g_bar_arrive = 0u;
            __threadfence();
            g_bar_gen = gen + 1u;
        } else {
            while (g_bar_gen == gen) { __nanosleep(32); }
        }
        __threadfence();
    }
    __syncthreads();
}

// ---------------- bf16 helpers ----------------
// pack two fp32 -> bf16x2 word; LOWER half = lo (lower-k element)
__device__ __forceinline__ uint32_t packbf(float lo, float hi)
{
    uint32_t u;
    asm("cvt.rn.bf16x2.f32 %0, %1, %2;" : "=r"(u) : "f"(hi), "f"(lo));
    return u;
}

__device__ __forceinline__ void mma_bf16(float* c, const uint32_t* a, uint2 b)
{
    asm volatile(
        "mma.sync.aligned.m16n8k16.row.col.f32.bf16.bf16.f32 "
        "{%0,%1,%2,%3}, {%4,%5,%6,%7}, {%8,%9}, {%0,%1,%2,%3};"
        : "+f"(c[0]), "+f"(c[1]), "+f"(c[2]), "+f"(c[3])
        : "r"(a[0]), "r"(a[1]), "r"(a[2]), "r"(a[3]), "r"(b.x), "r"(b.y));
}

// ---------------------------------------------------------------
// Fragment layouts (bf16x2 words):
//  A matrix [M x K]: block (mtile=m>>4, k16=k>>4), blocks mtile-major:
//    word = (mtile*(K/16)+k16)*128 + r*32 + (m&7)*4 + ((k>>1)&3)
//    r = ((m>>3)&1) + 2*((k>>3)&1)
//  B (weights) [N x K]: block (ntile=n>>3, k16):
//    word = (ntile*(K/16)+k16)*64 + ((n&7)*4 + ((k>>1)&3))*2 + ((k>>3)&1)
//    -> per-lane LDG.64 gives {b0,b1} directly.
// ---------------------------------------------------------------
// bf16 mma block tile, BM=128, BN=WN*NT*8, 256 threads (WM x WN warps).
// A from fragment-order global via double-buffered smem memcpy (SK k16's
// per stage); B direct from L2 (prepacked). OUTMODE: 0 = fp32 C (+bias),
// 1 = fp32 C with split bias (head), 2 = bf16-frag output with ReLU.
template<int MT, int NT, int WM, int WN, int SK, int OUTMODE>
__device__ __forceinline__ void mma_tile_bf16(
    const uint32_t* __restrict__ Af, const uint32_t* __restrict__ Bf,
    const float* __restrict__ b0v, const float* __restrict__ b1v,
    float* __restrict__ C, int ldc,
    uint32_t* __restrict__ Of, int o_nk16,
    int K, int bm, int bn, uint32_t* __restrict__ Asm)
{
    const int NK16 = K / 16;
    const int S = NK16 / SK;
    const int tid = threadIdx.x;
    const int lane = tid & 31;
    const int wid = tid >> 5;
    const int wm = wid / WN, wn = wid % WN;
    const int bn8 = bn >> 3;
    const int mtile0 = bm >> 4;

    float acc[MT][NT][4];
#pragma unroll
    for (int mt = 0; mt < MT; mt++)
#pragma unroll
        for (int nt = 0; nt < NT; nt++)
#pragma unroll
            for (int r = 0; r < 4; r++) acc[mt][nt][r] = 0.f;

    // prologue: stage 0 -> smem buffer 0
    {
        uint4 st[SK];
#pragma unroll
        for (int j = 0; j < SK; j++) {
            const int u = j * 256 + tid;
            const int blk = u >> 5, off = u & 31;
            const int mt = blk & 7, kl = blk >> 3;
            st[j] = *reinterpret_cast<const uint4*>(
                Af + ((size_t)(mtile0 + mt) * NK16 + kl) * 128 + off * 4);
        }
#pragma unroll
        for (int j = 0; j < SK; j++)
            reinterpret_cast<uint4*>(Asm)[j * 256 + tid] = st[j];
    }
    __syncthreads();

    for (int s = 0; s < S; s++) {
        uint32_t* cbuf = Asm + (s & 1) * (SK * 1024);
        uint32_t* nbuf = Asm + ((s + 1) & 1) * (SK * 1024);
        uint4 nx[SK];
        if (s + 1 < S) {
#pragma unroll
            for (int j = 0; j < SK; j++) {
                const int u = j * 256 + tid;
                const int blk = u >> 5, off = u & 31;
                const int mt = blk & 7, kl = blk >> 3;
                nx[j] = *reinterpret_cast<const uint4*>(
                    Af + ((size_t)(mtile0 + mt) * NK16 + (s + 1) * SK + kl) * 128
                       + off * 4);
            }
        }
#pragma unroll
        for (int kl = 0; kl < SK; kl++) {
            const int k16 = s * SK + kl;
            uint2 bfr[NT];
#pragma unroll
            for (int nt = 0; nt < NT; nt++)
                bfr[nt] = *reinterpret_cast<const uint2*>(
                    Bf + ((size_t)(bn8 + wn * NT + nt) * NK16 + k16) * 64
                       + lane * 2);
            uint32_t afr[MT][4];
#pragma unroll
            for (int mt = 0; mt < MT; mt++)
#pragma unroll
                for (int r = 0; r < 4; r++)
                    afr[mt][r] = cbuf[(kl * 8 + wm * MT + mt) * 128 + r * 32 + lane];
#pragma unroll
            for (int mt = 0; mt < MT; mt++)
#pragma unroll
                for (int nt = 0; nt < NT; nt++)
                    mma_bf16(acc[mt][nt], afr[mt], bfr[nt]);
        }
        if (s + 1 < S) {
#pragma unroll
            for (int j = 0; j < SK; j++)
                reinterpret_cast<uint4*>(nbuf)[j * 256 + tid] = nx[j];
        }
        __syncthreads();
    }

    // epilogue
    const int g = lane >> 2, tig = lane & 3;
#pragma unroll
    for (int mt = 0; mt < MT; mt++) {
#pragma unroll
        for (int nt = 0; nt < NT; nt++) {
            const int m0 = bm + (wm * MT + mt) * 16 + g;
            const int col = (wn * NT + nt) * 8 + 2 * tig;   // tile-local
            float bb0, bb1;
            if (OUTMODE == 1) {
                bb0 = (col < 32) ? b0v[col] : b1v[col - 32];
                bb1 = (col + 1 < 32) ? b0v[col + 1] : b1v[col + 1 - 32];
            } else {
                bb0 = b0v[bn + col];
                bb1 = b0v[bn + col + 1];
            }
            float v00 = acc[mt][nt][0] + bb0, v01 = acc[mt][nt][1] + bb1;
            float v10 = acc[mt][nt][2] + bb0, v11 = acc[mt][nt][3] + bb1;
            if (OUTMODE == 2) {
                v00 = fmaxf(v00, 0.f); v01 = fmaxf(v01, 0.f);
                v10 = fmaxf(v10, 0.f); v11 = fmaxf(v11, 0.f);
                const int kc = bn + col;
                const size_t w = ((size_t)(m0 >> 4) * o_nk16 + (kc >> 4)) * 128
                                 + ((kc >> 3) & 1) * 64 + (m0 & 7) * 4 + tig;
                Of[w]      = packbf(v00, v01);   // rows m0   (r = 2*kb)
                Of[w + 32] = packbf(v10, v11);   // rows m0+8 (r = 2*kb+1)
            } else {
                *reinterpret_cast<float2*>(C + (size_t)m0 * ldc + bn + col) =
                    make_float2(v00, v01);
                *reinterpret_cast<float2*>(C + (size_t)(m0 + 8) * ldc + bn + col) =
                    make_float2(v10, v11);
            }
        }
    }
}

// ---------------------------------------------------------------
// GRU gate fuse: 8 elements per thread; writes fp32 h + bf16 fragment word.
// NOTE: no early return (persistent kernel has grid_syncs after this).
// ---------------------------------------------------------------
__device__ __forceinline__ void gate_phase(
    const float* __restrict__ gi, const float* __restrict__ gh,
    float* __restrict__ h, uint32_t* __restrict__ hf,
    uint32_t* __restrict__ slotf)
{
    const int idx = blockIdx.x * blockDim.x + threadIdx.x;
    if (idx < B_ * R_ / 8) {
        const int b = idx >> 6, jb = idx & 63, j0 = jb << 3;
        const float* gib = gi + (size_t)b * R3_ + j0;
        const float* ghb = gh + (size_t)b * R3_ + j0;
        float* hb = h + (size_t)b * R_ + j0;
        float ir[8], iz[8], in_[8], hr[8], hz[8], hn[8], ho[8], hv[8];
        *(float4*)(ir)      = *(const float4*)(gib);
        *(float4*)(ir + 4)  = *(const float4*)(gib + 4);
        *(float4*)(iz)      = *(const float4*)(gib + R_);
        *(float4*)(iz + 4)  = *(const float4*)(gib + R_ + 4);
        *(float4*)(in_)     = *(const float4*)(gib + 2 * R_);
        *(float4*)(in_ + 4) = *(const float4*)(gib + 2 * R_ + 4);
        *(float4*)(hr)      = *(const float4*)(ghb);
        *(float4*)(hr + 4)  = *(const float4*)(ghb + 4);
        *(float4*)(hz)      = *(const float4*)(ghb + R_);
        *(float4*)(hz + 4)  = *(const float4*)(ghb + R_ + 4);
        *(float4*)(hn)      = *(const float4*)(ghb + 2 * R_);
        *(float4*)(hn + 4)  = *(const float4*)(ghb + 2 * R_ + 4);
        *(float4*)(ho)      = *(const float4*)(hb);
        *(float4*)(ho + 4)  = *(const float4*)(hb + 4);
#pragma unroll
        for (int i = 0; i < 8; i++) {
            const float r = 1.f / (1.f + expf(-(ir[i] + hr[i])));
            const float z = 1.f / (1.f + expf(-(iz[i] + hz[i])));
            const float n = tanhf(in_[i] + r * hn[i]);
            hv[i] = (1.f - z) * n + z * ho[i];
        }
        *(float4*)(hb)     = make_float4(hv[0], hv[1], hv[2], hv[3]);
        *(float4*)(hb + 4) = make_float4(hv[4], hv[5], hv[6], hv[7]);
        uint4 pk = make_uint4(packbf(hv[0], hv[1]), packbf(hv[2], hv[3]),
                              packbf(hv[4], hv[5]), packbf(hv[6], hv[7]));
        // fragment word/4: blk=(b>>4)*32+(jb>>1); r=((b>>3)&1)+2*(jb&1)
        const size_t w4 = ((size_t)(b >> 4) * 32 + (jb >> 1)) * 32
                          + (((b >> 3) & 1) + 2 * (jb & 1)) * 8 + (b & 7);
        reinterpret_cast<uint4*>(hf)[w4] = pk;
        if (slotf) reinterpret_cast<uint4*>(slotf)[w4] = pk;
    }
}

// ---------------------------------------------------------------
// Persistent recurrence: whole T=256 scan in one launch.
// P0 = gh0(96) + gh1(96) + gi0(96,K=32) = 288 tiles; P2 = gi1(96).
// ---------------------------------------------------------------
__global__ void __launch_bounds__(256, 2) rnn_persistent(
    const float* __restrict__ bih0, const float* __restrict__ bhh0,
    const float* __restrict__ bih1, const float* __restrict__ bhh1)
{
    __shared__ uint32_t Asm[2 * 4 * 1024];   // 32 KB
    const int bid = blockIdx.x;

    for (int t = 0; t < T_; t++) {
        // ---- P0 ----
        if (bid < 288) {
            const int grp = bid / 96, tt = bid % 96;
            const int bm = (tt / 12) * 128;
            const int bn = (tt % 12) * 128;
            if (grp == 0)
                mma_tile_bf16<4, 4, 2, 4, 4, 0>(g_h0f, g_whh0f, bhh0, nullptr,
                    g_gh, R3_, nullptr, 0, R_, bm, bn, Asm);
            else if (grp == 1)
                mma_tile_bf16<4, 4, 2, 4, 4, 0>(g_h1f, g_whh1f, bhh1, nullptr,
                    g_gh1, R3_, nullptr, 0, R_, bm, bn, Asm);
            else
                mma_tile_bf16<4, 4, 2, 4, 2, 0>(g_yf + (size_t)t * (B_ * Y_ / 2),
                    g_wih0f, bih0, nullptr, g_gi, R3_, nullptr, 0, Y_, bm, bn, Asm);
        }
        grid_sync();

        // ---- P1: gate layer 0 -> new h0 (fp32 + frag) ----
        gate_phase(g_gi, g_gh, g_h0, g_h0f, nullptr);
        grid_sync();

        // ---- P2: gi1 = h0' @ wih1^T ----
        if (bid < 96) {
            const int bm = (bid / 12) * 128;
            const int bn = (bid % 12) * 128;
            mma_tile_bf16<4, 4, 2, 4, 4, 0>(g_h0f, g_wih1f, bih1, nullptr,
                g_gi, R3_, nullptr, 0, R_, bm, bn, Asm);
        }
        grid_sync();

        // ---- P3: gate layer 1 -> new h1 (+ h1all slot t+1) ----
        uint32_t* slot = (t + 1 < T_)
            ? (g_h1allf + (size_t)(t + 1) * (B_ * R_ / 2)) : nullptr;
        gate_phase(g_gi, g_gh1, g_h1, g_h1f, slot);
        grid_sync();
    }
}

// ---------------------------------------------------------------
// Decoder GEMM: frag-A @ prepacked-W -> frag output, ReLU. 128x128 tiles.
__global__ void __launch_bounds__(256, 2) dec_gemm(
    const uint32_t* __restrict__ Af, const uint32_t* __restrict__ Bf,
    const float* __restrict__ bias, uint32_t* __restrict__ Of, int K)
{
    __shared__ uint32_t Asm[2 * 4 * 1024];
    const int bm = blockIdx.y * 128;
    const int bn = blockIdx.x * 128;
    mma_tile_bf16<4, 4, 2, 4, 4, 2>(Af, Bf, bias, nullptr, nullptr, 0,
                                    Of, H_ / 16, K, bm, bn, Asm);
}

// Head GEMM: d2f @ [mean_w; std_w] -> ms fp32 [rows][64]. 128x64 tiles.
__global__ void __launch_bounds__(256, 2) head_gemm(
    const uint32_t* __restrict__ d2f, const uint32_t* __restrict__ mswf,
    const float* __restrict__ mb, const float* __restrict__ sb,
    float* __restrict__ ms)
{
    __shared__ uint32_t Asm[2 * 4 * 1024];
    const int bm = blockIdx.x * 128;
    mma_tile_bf16<2, 4, 4, 2, 4, 1>(d2f, mswf, mb, sb, ms, 64,
                                    nullptr, 0, H_, bm, 0, Asm);
}

// NLL per row: one warp per row, reads ms fp32.
__global__ void __launch_bounds__(256) nll_kernel(
    const float* __restrict__ ms, const float* __restrict__ ybase,
    float* __restrict__ rowsum)
{
    const int row = blockIdx.x * 8 + (threadIdx.x >> 5);
    const int lane = threadIdx.x & 31;
    const float* m = ms + (size_t)row * 64;
    const float mean = m[lane];
    const float sraw = m[32 + lane];
    const float stdv = (sraw > 20.f) ? sraw : log1pf(expf(sraw));
    const float yv = ybase[(size_t)row * Y_ + lane];
    const float diff = yv - mean;
    float term = diff * diff / (stdv * stdv) + 2.f * logf(stdv)
                 + 1.8378770664093453f;  // log(2*pi)
#pragma unroll
    for (int o = 16; o > 0; o >>= 1)
        term += __shfl_down_sync(0xffffffffu, term, o);
    if (lane == 0) rowsum[row] = 0.5f * term;
}

// ---------------------------------------------------------------
// Weight prepack: W[N x K] fp32 -> bf16 B-fragment order.
__global__ void prepack_w(const float* __restrict__ W, uint32_t* __restrict__ out,
                          int N, int K)
{
    const int idx = blockIdx.x * blockDim.x + threadIdx.x;
    if (idx >= N * K / 2) return;
    const int n = idx / (K / 2), p = idx % (K / 2);
    const int k = p * 2;
    const uint32_t w = packbf(W[(size_t)n * K + k], W[(size_t)n * K + k + 1]);
    const int ntile = n >> 3, g = n & 7;
    const int tig = p & 3, reg = (p >> 2) & 1, k16 = p >> 3;
    out[((size_t)ntile * (K / 16) + k16) * 64 + (g * 4 + tig) * 2 + reg] = w;
}

// y prepack: y[T][B][Y] fp32 -> per-t A-fragment order bf16.
__global__ void prepack_y(const float* __restrict__ y, uint32_t* __restrict__ out)
{
    const int idx = blockIdx.x * blockDim.x + threadIdx.x;
    if (idx >= T_ * B_ * Y_ / 2) return;
    const int p = idx & 15, b = (idx >> 4) & 1023, t = idx >> 14;
    const int k = p * 2;
    const float* yp = y + ((size_t)t * B_ + b) * Y_ + k;
    const uint32_t w = packbf(yp[0], yp[1]);
    const int k16 = p >> 3, kb = (p >> 2) & 1, tig = p & 3;
    const int r = ((b >> 3) & 1) + 2 * kb;
    const size_t word = (((size_t)t * 64 + (b >> 4)) * 2 + k16) * 128
                        + r * 32 + (b & 7) * 4 + tig;
    out[word] = w;
}

// init: zero states (fp32 + frag) and h1all slot 0.
__global__ void init_kernel()
{
    const int idx = blockIdx.x * blockDim.x + threadIdx.x;
    if (idx < B_ * R_) {
        g_h0[idx] = 0.f;
        g_h1[idx] = 0.f;
    }
    if (idx < B_ * R_ / 2) {
        g_h0f[idx] = 0u;
        g_h1f[idx] = 0u;
        g_h1allf[idx] = 0u;
    }
}

// Deterministic final reduction (fixed-order tree, fp64 accumulate)
__global__ void __launch_bounds__(1024) reduce_kernel(float* __restrict__ out)
{
    __shared__ double sh[1024];
    double s = 0.0;
    for (int i = threadIdx.x; i < T_ * B_; i += 1024)
        s += (double)g_rowsum[i];
    sh[threadIdx.x] = s;
    __syncthreads();
    for (int o = 512; o > 0; o >>= 1) {
        if (threadIdx.x < o) sh[threadIdx.x] += sh[threadIdx.x + o];
        __syncthreads();
    }
    if (threadIdx.x == 0) out[0] = (float)sh[0];
}

// ---------------------------------------------------------------
extern "C" void kernel_launch(void* const* d_in, const int* in_sizes, int n_in,
                              void* d_out, int out_size)
{
    const float* y      = (const float*)d_in[0];
    const float* dec_w1 = (const float*)d_in[1];
    const float* dec_b1 = (const float*)d_in[2];
    const float* dec_w2 = (const float*)d_in[3];
    const float* dec_b2 = (const float*)d_in[4];
    const float* mean_w = (const float*)d_in[5];
    const float* mean_b = (const float*)d_in[6];
    const float* std_w  = (const float*)d_in[7];
    const float* std_b  = (const float*)d_in[8];
    const float* wih0   = (const float*)d_in[9];
    const float* whh0   = (const float*)d_in[10];
    const float* bih0   = (const float*)d_in[11];
    const float* bhh0   = (const float*)d_in[12];
    const float* wih1   = (const float*)d_in[13];
    const float* whh1   = (const float*)d_in[14];
    const float* bih1   = (const float*)d_in[15];
    const float* bhh1   = (const float*)d_in[16];
    float* out = (float*)d_out;

    uint32_t *pwhh0f, *pwih0f, *pwih1f, *pwhh1f, *pw1f, *pw2f, *pmswf;
    uint32_t *pyf, *ph1allf, *pd1f, *pd2f;
    float *pms, *prow;
    cudaGetSymbolAddress((void**)&pwhh0f, g_whh0f);
    cudaGetSymbolAddress((void**)&pwih0f, g_wih0f);
    cudaGetSymbolAddress((void**)&pwih1f, g_wih1f);
    cudaGetSymbolAddress((void**)&pwhh1f, g_whh1f);
    cudaGetSymbolAddress((void**)&pw1f, g_w1f);
    cudaGetSymbolAddress((void**)&pw2f, g_w2f);
    cudaGetSymbolAddress((void**)&pmswf, g_mswf);
    cudaGetSymbolAddress((void**)&pyf, g_yf);
    cudaGetSymbolAddress((void**)&ph1allf, g_h1allf);
    cudaGetSymbolAddress((void**)&pd1f, g_d1f);
    cudaGetSymbolAddress((void**)&pd2f, g_d2f);
    cudaGetSymbolAddress((void**)&pms, g_ms);
    cudaGetSymbolAddress((void**)&prow, g_rowsum);

    // ---- prepacks (run each replay; ~100 us total) ----
    auto blocks = [](int n) { return (n + 255) / 256; };
    prepack_w<<<blocks(R3_ * R_ / 2), 256>>>(whh0, pwhh0f, R3_, R_);
    prepack_w<<<blocks(R3_ * Y_ / 2), 256>>>(wih0, pwih0f, R3_, Y_);
    prepack_w<<<blocks(R3_ * R_ / 2), 256>>>(wih1, pwih1f, R3_, R_);
    prepack_w<<<blocks(R3_ * R_ / 2), 256>>>(whh1, pwhh1f, R3_, R_);
    prepack_w<<<blocks(H_ * R_ / 2), 256>>>(dec_w1, pw1f, H_, R_);
    prepack_w<<<blocks(H_ * H_ / 2), 256>>>(dec_w2, pw2f, H_, H_);
    prepack_w<<<blocks(32 * H_ / 2), 256>>>(mean_w, pmswf, 32, H_);
    prepack_w<<<blocks(32 * H_ / 2), 256>>>(std_w, pmswf + 4 * (H_ / 16) * 64, 32, H_);
    prepack_y<<<blocks(T_ * B_ * Y_ / 2), 256>>>(y, pyf);
    init_kernel<<<blocks(B_ * R_), 256>>>();

    // ---- sequential scan (one persistent kernel) ----
    rnn_persistent<<<NBLK_, 256>>>(bih0, bhh0, bih1, bhh1);

    // ---- decoder + NLL (big parallel GEMMs, chunked) ----
    const dim3 gdec(H_ / 128, ROWS_ / 128);  // (8, 256)
    for (int c = 0; c < NCHUNK_; c++) {
        dec_gemm<<<gdec, 256>>>(ph1allf + (size_t)c * (ROWS_ * R_ / 2),
                                pw1f, dec_b1, pd1f, R_);
        dec_gemm<<<gdec, 256>>>(pd1f, pw2f, dec_b2, pd2f, H_);
        head_gemm<<<ROWS_ / 128, 256>>>(pd2f, pmswf, mean_b, std_b, pms);
        nll_kernel<<<ROWS_ / 8, 256>>>(pms, y + (size_t)c * ROWS_ * Y_,
                                       prow + (size_t)c * ROWS_);
    }
    reduce_kernel<<<1, 1024>>>(out);
}